// round 2
// baseline (speedup 1.0000x reference)
#include <cuda_runtime.h>
#include <cuda_bf16.h>

// IoUMetricLoss: pred_label fp32 [8,19,512,1024], label int32 [8,512,1024]
// (JAX default config demotes the reference's jnp.int64 to int32.)
// out: scalar fp32 = 1 - nanmean(IoU per class), all-NaN -> 0.5
//
// HBM-bound: ~335 MB mandatory reads. float4-vectorized argmax
// (4 pixels/thread), per-warp replicated smem histograms with packed
// 64-bit label+intersect counters, 3-kernel graph (zero / hist / finalize).

#define NUM_CLASSES 19
#define HW_SHIFT 19                  // 512*1024 = 2^19
#define HW (1 << HW_SHIFT)
#define BATCH 8
#define TOTAL_PIX (BATCH * HW)       // 4194304
#define VEC_GROUPS (TOTAL_PIX / 4)   // 1048576
#define HIST_BLOCK 256
#define WARPS_PER_BLOCK (HIST_BLOCK / 32)

// Global accumulators (no cudaMalloc allowed).
// g_li[c]: low 32 bits = area_label count, high 32 bits = area_intersect count.
__device__ unsigned long long g_li[NUM_CLASSES];
__device__ unsigned int       g_pred[NUM_CLASSES];

__global__ void iou_zero_kernel() {
    int t = threadIdx.x;
    if (t < NUM_CLASSES) {
        g_li[t]   = 0ULL;
        g_pred[t] = 0u;
    }
}

__global__ void __launch_bounds__(HIST_BLOCK)
iou_hist_kernel(const float* __restrict__ pred,
                const int* __restrict__ label) {
    __shared__ unsigned long long s_li[WARPS_PER_BLOCK][NUM_CLASSES];
    __shared__ unsigned int       s_pr[WARPS_PER_BLOCK][NUM_CLASSES];

    const int warp = threadIdx.x >> 5;
    const int lane = threadIdx.x & 31;

    // zero this warp's private histogram
    if (lane < NUM_CLASSES) {
        s_li[warp][lane] = 0ULL;
        s_pr[warp][lane] = 0u;
    }
    __syncwarp();

    const unsigned stride = gridDim.x * blockDim.x;
    for (unsigned g = blockIdx.x * blockDim.x + threadIdx.x;
         g < VEC_GROUPS; g += stride) {
        const unsigned P  = g << 2;             // first pixel of this group
        const unsigned b  = P >> HW_SHIFT;      // batch index
        const unsigned hw = P & (HW - 1);       // position within plane

        const float* base = pred + ((size_t)b * NUM_CLASSES << HW_SHIFT) + hw;

        // argmax over 19 classes for 4 pixels, first-max-wins (strict >)
        float4 bv = *(const float4*)base;
        int i0 = 0, i1 = 0, i2 = 0, i3 = 0;
        #pragma unroll
        for (int c = 1; c < NUM_CLASSES; c++) {
            float4 v = *(const float4*)(base + ((size_t)c << HW_SHIFT));
            if (v.x > bv.x) { bv.x = v.x; i0 = c; }
            if (v.y > bv.y) { bv.y = v.y; i1 = c; }
            if (v.z > bv.z) { bv.z = v.z; i2 = c; }
            if (v.w > bv.w) { bv.w = v.w; i3 = c; }
        }

        // labels: 4 consecutive int32 = one 16B load
        int4 lv = *(const int4*)(label + P);
        int l0 = lv.x, l1 = lv.y, l2 = lv.z, l3 = lv.w;

        // accumulate: packed label(+intersect) atomic + pred atomic, per pixel
        if (l0 >= 0) {
            atomicAdd(&s_li[warp][l0], 1ULL | ((i0 == l0) ? (1ULL << 32) : 0ULL));
            atomicAdd(&s_pr[warp][i0], 1u);
        }
        if (l1 >= 0) {
            atomicAdd(&s_li[warp][l1], 1ULL | ((i1 == l1) ? (1ULL << 32) : 0ULL));
            atomicAdd(&s_pr[warp][i1], 1u);
        }
        if (l2 >= 0) {
            atomicAdd(&s_li[warp][l2], 1ULL | ((i2 == l2) ? (1ULL << 32) : 0ULL));
            atomicAdd(&s_pr[warp][i2], 1u);
        }
        if (l3 >= 0) {
            atomicAdd(&s_li[warp][l3], 1ULL | ((i3 == l3) ? (1ULL << 32) : 0ULL));
            atomicAdd(&s_pr[warp][i3], 1u);
        }
    }
    __syncthreads();

    // block reduce: one global atomic per class per counter
    if (threadIdx.x < NUM_CLASSES) {
        unsigned long long li = 0ULL;
        unsigned int       pr = 0u;
        #pragma unroll
        for (int w = 0; w < WARPS_PER_BLOCK; w++) {
            li += s_li[w][threadIdx.x];
            pr += s_pr[w][threadIdx.x];
        }
        atomicAdd(&g_li[threadIdx.x], li);
        atomicAdd(&g_pred[threadIdx.x], pr);
    }
}

__global__ void iou_finalize_kernel(float* __restrict__ out) {
    const int c = threadIdx.x;  // 32 threads, classes 0..18 active
    float iou_sum = 0.0f;
    int   valid   = 0;
    if (c < NUM_CLASSES) {
        unsigned long long li = g_li[c];
        unsigned int lab   = (unsigned int)(li & 0xFFFFFFFFULL);
        unsigned int inter = (unsigned int)(li >> 32);
        unsigned int pr    = g_pred[c];
        unsigned long long uni =
            (unsigned long long)lab + (unsigned long long)pr
            - (unsigned long long)inter;
        if (uni > 0ULL) {
            iou_sum = (float)inter / (float)uni;
            valid   = 1;
        }
        // uni == 0 -> 0/0 = NaN in reference, excluded by nanmean
    }
    #pragma unroll
    for (int o = 16; o > 0; o >>= 1) {
        iou_sum += __shfl_down_sync(0xFFFFFFFFu, iou_sum, o);
        valid   += __shfl_down_sync(0xFFFFFFFFu, valid, o);
    }
    if (c == 0) {
        // nanmean; all-NaN -> result 0.5 -> loss 0.5
        float loss = (valid > 0) ? (1.0f - iou_sum / (float)valid) : 0.5f;
        *out = loss;
    }
}

extern "C" void kernel_launch(void* const* d_in, const int* in_sizes, int n_in,
                              void* d_out, int out_size) {
    // Defensive input resolution by element count:
    // pred = 8*19*512*1024 = 79,691,776 elems; label = 8*512*1024 = 4,194,304.
    const void* p0 = d_in[0];
    const void* p1 = d_in[1];
    const float* pred;
    const int*   label;
    if (in_sizes[0] >= in_sizes[1]) {
        pred  = (const float*)p0;
        label = (const int*)p1;
    } else {
        pred  = (const float*)p1;
        label = (const int*)p0;
    }
    float* out = (float*)d_out;

    iou_zero_kernel<<<1, 32>>>();
    // 4096 blocks x 256 threads = 1,048,576 threads = exactly one vec4
    // group per thread (grid-stride loop kept for safety).
    iou_hist_kernel<<<4096, HIST_BLOCK>>>(pred, label);
    iou_finalize_kernel<<<1, 32>>>(out);
}

// round 3
// speedup vs baseline: 1.0262x; 1.0262x over previous
#include <cuda_runtime.h>
#include <cuda_bf16.h>

// IoUMetricLoss: pred_label fp32 [8,19,512,1024], label int32 [8,512,1024]
// out: scalar fp32 = 1 - nanmean(IoU per class), all-NaN -> 0.5
//
// Single fused kernel (R3): hist + last-block finalize + self-reset
// accumulators. ~335 MB streamed once; main loop runs at ~6 TB/s (LTS cap),
// so the win here is removing the zero/finalize launch overhead (~6 us).

#define NUM_CLASSES 19
#define HW_SHIFT 19                  // 512*1024 = 2^19
#define HW (1 << HW_SHIFT)
#define BATCH 8
#define TOTAL_PIX (BATCH * HW)       // 4194304
#define VEC_GROUPS (TOTAL_PIX / 4)   // 1048576
#define HIST_BLOCK 256
#define WARPS_PER_BLOCK (HIST_BLOCK / 32)
#define GRID_BLOCKS 4096

// Global accumulators (no cudaMalloc allowed). Statically zero-initialized;
// the finalizing block re-zeros them each run so graph replays are clean.
// g_li[c]: low 32 bits = area_label count, high 32 bits = area_intersect.
__device__ unsigned long long g_li[NUM_CLASSES];
__device__ unsigned int       g_pred[NUM_CLASSES];
__device__ unsigned int       g_done;

__global__ void __launch_bounds__(HIST_BLOCK)
iou_fused_kernel(const float* __restrict__ pred,
                 const int* __restrict__ label,
                 float* __restrict__ out) {
    __shared__ unsigned long long s_li[WARPS_PER_BLOCK][NUM_CLASSES];
    __shared__ unsigned int       s_pr[WARPS_PER_BLOCK][NUM_CLASSES];
    __shared__ int                s_is_last;

    const int warp = threadIdx.x >> 5;
    const int lane = threadIdx.x & 31;

    // zero this warp's private histogram
    if (lane < NUM_CLASSES) {
        s_li[warp][lane] = 0ULL;
        s_pr[warp][lane] = 0u;
    }
    __syncwarp();

    const unsigned stride = gridDim.x * blockDim.x;
    for (unsigned g = blockIdx.x * blockDim.x + threadIdx.x;
         g < VEC_GROUPS; g += stride) {
        const unsigned P  = g << 2;             // first pixel of this group
        const unsigned b  = P >> HW_SHIFT;      // batch index
        const unsigned hw = P & (HW - 1);       // position within plane

        const float* base = pred + ((size_t)b * NUM_CLASSES << HW_SHIFT) + hw;

        // argmax over 19 classes for 4 pixels, first-max-wins (strict >).
        // __ldcs: streamed-once data, evict-first.
        float4 bv = __ldcs((const float4*)base);
        int i0 = 0, i1 = 0, i2 = 0, i3 = 0;
        #pragma unroll
        for (int c = 1; c < NUM_CLASSES; c++) {
            float4 v = __ldcs((const float4*)(base + ((size_t)c << HW_SHIFT)));
            if (v.x > bv.x) { bv.x = v.x; i0 = c; }
            if (v.y > bv.y) { bv.y = v.y; i1 = c; }
            if (v.z > bv.z) { bv.z = v.z; i2 = c; }
            if (v.w > bv.w) { bv.w = v.w; i3 = c; }
        }

        // labels: 4 consecutive int32 = one 16B load
        int4 lv = __ldcs((const int4*)(label + P));
        int l0 = lv.x, l1 = lv.y, l2 = lv.z, l3 = lv.w;

        // accumulate: packed label(+intersect) atomic + pred atomic, per pixel
        if (l0 >= 0) {
            atomicAdd(&s_li[warp][l0], 1ULL | ((i0 == l0) ? (1ULL << 32) : 0ULL));
            atomicAdd(&s_pr[warp][i0], 1u);
        }
        if (l1 >= 0) {
            atomicAdd(&s_li[warp][l1], 1ULL | ((i1 == l1) ? (1ULL << 32) : 0ULL));
            atomicAdd(&s_pr[warp][i1], 1u);
        }
        if (l2 >= 0) {
            atomicAdd(&s_li[warp][l2], 1ULL | ((i2 == l2) ? (1ULL << 32) : 0ULL));
            atomicAdd(&s_pr[warp][i2], 1u);
        }
        if (l3 >= 0) {
            atomicAdd(&s_li[warp][l3], 1ULL | ((i3 == l3) ? (1ULL << 32) : 0ULL));
            atomicAdd(&s_pr[warp][i3], 1u);
        }
    }
    __syncthreads();

    // block reduce: one global atomic per class per counter
    if (threadIdx.x < NUM_CLASSES) {
        unsigned long long li = 0ULL;
        unsigned int       pr = 0u;
        #pragma unroll
        for (int w = 0; w < WARPS_PER_BLOCK; w++) {
            li += s_li[w][threadIdx.x];
            pr += s_pr[w][threadIdx.x];
        }
        atomicAdd(&g_li[threadIdx.x], li);
        atomicAdd(&g_pred[threadIdx.x], pr);
    }
    __syncthreads();

    // last-block-done: the final block to arrive finalizes + resets state
    if (threadIdx.x == 0) {
        __threadfence();
        unsigned prev = atomicAdd(&g_done, 1u);
        s_is_last = (prev == gridDim.x - 1);
    }
    __syncthreads();
    if (!s_is_last) return;

    if (threadIdx.x < 32) {
        const int c = threadIdx.x;
        float iou_sum = 0.0f;
        int   valid   = 0;
        unsigned long long li = 0ULL;
        unsigned int pr = 0u;
        if (c < NUM_CLASSES) {
            li = g_li[c];
            pr = g_pred[c];
            unsigned int lab   = (unsigned int)(li & 0xFFFFFFFFULL);
            unsigned int inter = (unsigned int)(li >> 32);
            unsigned long long uni =
                (unsigned long long)lab + (unsigned long long)pr
                - (unsigned long long)inter;
            if (uni > 0ULL) {
                iou_sum = (float)inter / (float)uni;
                valid   = 1;
            }
            // uni == 0 -> 0/0 = NaN in reference, excluded by nanmean
            // reset accumulators for the next graph replay
            g_li[c]   = 0ULL;
            g_pred[c] = 0u;
        }
        #pragma unroll
        for (int o = 16; o > 0; o >>= 1) {
            iou_sum += __shfl_down_sync(0xFFFFFFFFu, iou_sum, o);
            valid   += __shfl_down_sync(0xFFFFFFFFu, valid, o);
        }
        if (c == 0) {
            g_done = 0u;  // reset completion counter
            float loss = (valid > 0) ? (1.0f - iou_sum / (float)valid) : 0.5f;
            *out = loss;
        }
    }
}

extern "C" void kernel_launch(void* const* d_in, const int* in_sizes, int n_in,
                              void* d_out, int out_size) {
    // Defensive input resolution by element count:
    // pred = 8*19*512*1024 = 79,691,776 elems; label = 8*512*1024 = 4,194,304.
    const float* pred;
    const int*   label;
    if (in_sizes[0] >= in_sizes[1]) {
        pred  = (const float*)d_in[0];
        label = (const int*)d_in[1];
    } else {
        pred  = (const float*)d_in[1];
        label = (const int*)d_in[0];
    }
    float* out = (float*)d_out;

    iou_fused_kernel<<<GRID_BLOCKS, HIST_BLOCK>>>(pred, label, out);
}